// round 3
// baseline (speedup 1.0000x reference)
#include <cuda_runtime.h>
#include <cuda_bf16.h>

#define NN 16384      // nodes/edges (and bond_n rows A = 16384)
#define DD 128        // emb dim
// Only layer i = 2 matters: the reference loop does not feed h back.

#define NBLK 296      // 2 blocks per SM on 148 SMs, single wave

// Scratch (device globals — zero-initialized at module load)
__device__ float g_part[NBLK][NN];           // per-block column partial sums (19.4 MB)
__device__ float g_hn[(size_t)NN * DD];      // 8 MB
__device__ float g_mpart[128][DD];           // per-block partials of m
__device__ float g_mm[DD];
__device__ unsigned g_cnt;                   // last-block counter (self-resetting)

// ---------------------------------------------------------------------------
// FUSED kernel, 296 blocks (one full wave @ 2 blocks/SM):
//   blocks [0,128):   GEMM h_n = relu(cat @ Wi_w[2].T + b) for 128 rows,
//                     THEN stream 51 rows of bond_n (row-contiguous) -> partial.
//   blocks [128,296): stream 58-59 rows of bond_n -> partial.
// Row shares are sized so GEMM blocks (who start streaming ~20us late)
// finish together with pure-streaming blocks. All partials are written to a
// fixed per-block slot -> fully deterministic across graph replays.
// ---------------------------------------------------------------------------
__global__ void __launch_bounds__(256, 2) k_fused(
    const float* __restrict__ bn,
    const int* __restrict__ x, const int* __restrict__ ea,
    const float* __restrict__ aemb, const float* __restrict__ bemb,
    const float* __restrict__ Wi_w2, const float* __restrict__ Wi_b2)
{
    extern __shared__ float sm[];
    const int tid = threadIdx.x;
    const int bid = blockIdx.x;

    // ---- static row shares for the bond_n stream (sum = 16384) ----
    int start, cnt;
    if (bid < 128)          { start = bid * 51;                 cnt = 51; }
    else if (bid < 240)     { start = 6528  + (bid - 128) * 59; cnt = 59; }
    else                    { start = 13136 + (bid - 240) * 58; cnt = 58; }

    if (bid < 128) {
        // ---------------- GEMM phase (blocks 0..127) ----------------
        float* w_s   = sm;                 // [64][129]  = 33,024 B (per-k chunk)
        float* cat_s = sm + 64 * 129;      // [128][64]  = 32,768 B

        __shared__ float bias_s[128];
        __shared__ int xi0[128], xi1[128], ei0[128], ei1[128];

        const int rowBase = bid * 128;

        if (tid < 128) {
            bias_s[tid] = Wi_b2[tid];
            int r = rowBase + tid;
            xi0[tid] = x[2 * r];  xi1[tid] = x[2 * r + 1];
            ei0[tid] = ea[2 * r]; ei1[tid] = ea[2 * r + 1];
        }
        __syncthreads();

        const int tx = tid & 15, ty = tid >> 4;
        float acc[8][8];
#pragma unroll
        for (int i = 0; i < 8; i++)
#pragma unroll
            for (int j = 0; j < 8; j++) acc[i][j] = 0.f;

        for (int kc = 0; kc < 256; kc += 64) {
            for (int idx = tid; idx < 8192; idx += 256) {
                int d = idx >> 6, kk = idx & 63;
                w_s[kk * 129 + d] = Wi_w2[d * 256 + kc + kk];
            }
            const bool atom = (kc < 128);
            const float* emb = atom ? aemb : bemb;
            for (int idx = tid; idx < 2048; idx += 256) {
                int row  = idx >> 4;
                int kloc = (idx & 15) * 4;
                int i0 = atom ? xi0[row] : ei0[row];
                int i1 = atom ? xi1[row] : ei1[row];
                int ko = atom ? (kc + kloc) : (kc - 128 + kloc);
                float4 v0 = *(const float4*)(emb + i0 * 128 + ko);
                float4 v1 = *(const float4*)(emb + i1 * 128 + ko);
                float4 s;
                s.x = v0.x + v1.x; s.y = v0.y + v1.y;
                s.z = v0.z + v1.z; s.w = v0.w + v1.w;
                *(float4*)(cat_s + row * 64 + kloc) = s;
            }
            __syncthreads();

#pragma unroll 8
            for (int kk = 0; kk < 64; kk++) {
                const float* wr = w_s + kk * 129;
                float b[8], a[8];
#pragma unroll
                for (int j = 0; j < 8; j++) b[j] = wr[tx + 16 * j];
#pragma unroll
                for (int i = 0; i < 8; i++) a[i] = cat_s[(ty + 16 * i) * 64 + kk];
#pragma unroll
                for (int i = 0; i < 8; i++)
#pragma unroll
                    for (int j = 0; j < 8; j++)
                        acc[i][j] = fmaf(a[i], b[j], acc[i][j]);
            }
            __syncthreads();
        }

        // epilogue: bias + relu -> g_hn
#pragma unroll
        for (int i = 0; i < 8; i++) {
            int r = ty + 16 * i;
#pragma unroll
            for (int j = 0; j < 8; j++) {
                int d = tx + 16 * j;
                float v = acc[i][j] + bias_s[d];
                g_hn[(size_t)(rowBase + r) * 128 + d] = v > 0.f ? v : 0.f;
            }
        }
        // fall through to streaming tail
    }

    // ---------------- bond_n streaming (ALL blocks) ----------------
    // Row-contiguous: block reads rows [start, start+cnt), full 64KB width.
    // Column accumulators live in registers: col = tid*4 + i*1024, i<16.
    float4 acc[16];
#pragma unroll
    for (int i = 0; i < 16; i++) acc[i] = make_float4(0.f, 0.f, 0.f, 0.f);

    for (int r = 0; r < cnt; r++) {
        const float4* rp = (const float4*)(bn + (size_t)(start + r) * NN) + tid;
#pragma unroll
        for (int i = 0; i < 16; i++) {
            float4 v = __ldcs(rp + i * 256);
            acc[i].x += v.x; acc[i].y += v.y; acc[i].z += v.z; acc[i].w += v.w;
        }
    }
    float4* dst = (float4*)g_part[bid] + tid;
#pragma unroll
    for (int i = 0; i < 16; i++) dst[i * 256] = acc[i];
}

// ---------------------------------------------------------------------------
// k_m: colw[n] = sum over 296 block partials; m[d] = sum_n colw[n]*h_n[n,d]
//      via per-block partials; last block reduces + computes
//      mm = m @ Wm_w2.T + Wm_b2. Counter self-resets for graph replay.
// ---------------------------------------------------------------------------
__global__ void __launch_bounds__(256) k_m(const float* __restrict__ Wm_w2,
                                           const float* __restrict__ Wm_b2) {
    __shared__ float red[256];
    __shared__ float colw_s[128];
    __shared__ float ms[128];
    __shared__ bool last;

    const int b = blockIdx.x, tid = threadIdx.x;
    const int d = tid & 127, half = tid >> 7;
    const int rowBase = b * 128;

    // Stage 1: colw for this block's 128 rows (halves sum 148 partials each)
    {
        const int n = rowBase + d;
        float s = 0.f;
        const int u0 = half * 148;
#pragma unroll 4
        for (int u = u0; u < u0 + 148; u++) s += g_part[u][n];
        red[tid] = s;
    }
    __syncthreads();
    if (tid < 128) colw_s[tid] = red[tid] + red[tid + 128];
    __syncthreads();

    // Stage 2: m partial over this block's rows
    float p = 0.f;
#pragma unroll 4
    for (int r = 0; r < 64; r++) {
        int row = half * 64 + r;
        p = fmaf(colw_s[row], g_hn[(size_t)(rowBase + row) * DD + d], p);
    }
    red[tid] = p;
    __syncthreads();
    if (tid < 128) g_mpart[b][tid] = red[tid] + red[tid + 128];
    __threadfence();
    if (tid == 0) last = (atomicAdd(&g_cnt, 1u) == 127u);
    __syncthreads();

    if (last) {
        if (tid < 128) {
            float s = 0.f;
#pragma unroll 8
            for (int w = 0; w < 128; w++) s += __ldcg(&g_mpart[w][tid]);
            ms[tid] = s;
        }
        __syncthreads();
        if (tid < 128) {
            float s = Wm_b2[tid];
            const float* row = Wm_w2 + tid * 128;
#pragma unroll 8
            for (int k = 0; k < 128; k++) s = fmaf(ms[k], __ldg(row + k), s);
            g_mm[tid] = s;
        }
        if (tid == 0) g_cnt = 0u;   // reset for next graph replay
    }
}

// ---------------------------------------------------------------------------
// k_out: out = relu(h_n + mm[broadcast])
// ---------------------------------------------------------------------------
__global__ void __launch_bounds__(256) k_out(float* __restrict__ out) {
    __shared__ float mm[128];
    if (threadIdx.x < 128) mm[threadIdx.x] = g_mm[threadIdx.x];
    __syncthreads();
    size_t i = (size_t)blockIdx.x * 256 + threadIdx.x;   // float4 index
    float4 v = *(const float4*)(g_hn + i * 4);
    int d0 = (int)((i * 4) & 127);
    v.x = fmaxf(v.x + mm[d0 + 0], 0.f);
    v.y = fmaxf(v.y + mm[d0 + 1], 0.f);
    v.z = fmaxf(v.z + mm[d0 + 2], 0.f);
    v.w = fmaxf(v.w + mm[d0 + 3], 0.f);
    *((float4*)out + i) = v;
}

// ---------------------------------------------------------------------------
extern "C" void kernel_launch(void* const* d_in, const int* in_sizes, int n_in,
                              void* d_out, int out_size) {
    const int*   x    = (const int*)d_in[0];
    const int*   ea   = (const int*)d_in[1];
    const float* bn   = (const float*)d_in[2];
    const float* aemb = (const float*)d_in[3];
    const float* bemb = (const float*)d_in[4];
    const float* Wi_w = (const float*)d_in[5];
    const float* Wi_b = (const float*)d_in[6];
    const float* Wm_w = (const float*)d_in[7];
    const float* Wm_b = (const float*)d_in[8];

    // Only the last layer (i = 2) affects the output.
    const float* Wi_w2 = Wi_w + 2 * 128 * 256;
    const float* Wi_b2 = Wi_b + 2 * 128;
    const float* Wm_w2 = Wm_w + 2 * 128 * 128;
    const float* Wm_b2 = Wm_b + 2 * 128;

    const int smem = (64 * 129 + 128 * 64) * (int)sizeof(float);  // 65,792 B
    static bool attr_set = false;
    if (!attr_set) {
        cudaFuncSetAttribute(k_fused, cudaFuncAttributeMaxDynamicSharedMemorySize, smem);
        attr_set = true;
    }

    k_fused<<<NBLK, 256, smem>>>(bn, x, ea, aemb, bemb, Wi_w2, Wi_b2);
    k_m<<<128, 256>>>(Wm_w2, Wm_b2);
    k_out<<<2048, 256>>>((float*)d_out);
}

// round 4
// speedup vs baseline: 1.0292x; 1.0292x over previous
#include <cuda_runtime.h>
#include <cuda_bf16.h>

#define NN 16384      // nodes/edges (and bond_n rows A = 16384)
#define DD 128        // emb dim
// Only layer i = 2 matters: the reference loop does not feed h back.

#define NBLK 296      // 2 blocks per SM on 148 SMs, single wave
#define MBLK 256      // k_m grid

// Scratch (device globals — zero-initialized at module load)
__device__ float g_part[NBLK][NN];           // per-block column partial sums (19.4 MB)
__device__ float g_hn[(size_t)NN * DD];      // 8 MB
__device__ float g_mpartT[DD][MBLK];         // transposed m partials (contig per d)
__device__ float g_mm[DD];
__device__ unsigned g_cnt;                   // last-block counter (self-resetting)

// ---------------------------------------------------------------------------
// FUSED kernel, 296 blocks (one full wave @ 2 blocks/SM):
//   blocks [0,128):   GEMM h_n = relu(cat @ Wi_w[2].T + b) for 128 rows,
//                     THEN stream 51 rows of bond_n (row-contiguous).
//   blocks [128,296): stream 58-59 rows of bond_n.
// Deterministic static shares; per-block partials, no atomics.
// ---------------------------------------------------------------------------
__global__ void __launch_bounds__(256, 2) k_fused(
    const float* __restrict__ bn,
    const int* __restrict__ x, const int* __restrict__ ea,
    const float* __restrict__ aemb, const float* __restrict__ bemb,
    const float* __restrict__ Wi_w2, const float* __restrict__ Wi_b2)
{
    extern __shared__ float sm[];
    const int tid = threadIdx.x;
    const int bid = blockIdx.x;

    // ---- static row shares for the bond_n stream (sum = 16384) ----
    int start, cnt;
    if (bid < 128)          { start = bid * 51;                 cnt = 51; }
    else if (bid < 240)     { start = 6528  + (bid - 128) * 59; cnt = 59; }
    else                    { start = 13136 + (bid - 240) * 58; cnt = 58; }

    if (bid < 128) {
        // ---------------- GEMM phase (blocks 0..127) ----------------
        float* w_s   = sm;                 // [64][129]  = 33,024 B (per-k chunk)
        float* cat_s = sm + 64 * 129;      // [128][64]  = 32,768 B

        __shared__ float bias_s[128];
        __shared__ int xi0[128], xi1[128], ei0[128], ei1[128];

        const int rowBase = bid * 128;

        if (tid < 128) {
            bias_s[tid] = Wi_b2[tid];
            int r = rowBase + tid;
            xi0[tid] = x[2 * r];  xi1[tid] = x[2 * r + 1];
            ei0[tid] = ea[2 * r]; ei1[tid] = ea[2 * r + 1];
        }
        __syncthreads();

        const int tx = tid & 15, ty = tid >> 4;
        float acc[8][8];
#pragma unroll
        for (int i = 0; i < 8; i++)
#pragma unroll
            for (int j = 0; j < 8; j++) acc[i][j] = 0.f;

        for (int kc = 0; kc < 256; kc += 64) {
            for (int idx = tid; idx < 8192; idx += 256) {
                int d = idx >> 6, kk = idx & 63;
                w_s[kk * 129 + d] = Wi_w2[d * 256 + kc + kk];
            }
            const bool atom = (kc < 128);
            const float* emb = atom ? aemb : bemb;
            for (int idx = tid; idx < 2048; idx += 256) {
                int row  = idx >> 4;
                int kloc = (idx & 15) * 4;
                int i0 = atom ? xi0[row] : ei0[row];
                int i1 = atom ? xi1[row] : ei1[row];
                int ko = atom ? (kc + kloc) : (kc - 128 + kloc);
                float4 v0 = *(const float4*)(emb + i0 * 128 + ko);
                float4 v1 = *(const float4*)(emb + i1 * 128 + ko);
                float4 s;
                s.x = v0.x + v1.x; s.y = v0.y + v1.y;
                s.z = v0.z + v1.z; s.w = v0.w + v1.w;
                *(float4*)(cat_s + row * 64 + kloc) = s;
            }
            __syncthreads();

#pragma unroll 8
            for (int kk = 0; kk < 64; kk++) {
                const float* wr = w_s + kk * 129;
                float b[8], a[8];
#pragma unroll
                for (int j = 0; j < 8; j++) b[j] = wr[tx + 16 * j];
#pragma unroll
                for (int i = 0; i < 8; i++) a[i] = cat_s[(ty + 16 * i) * 64 + kk];
#pragma unroll
                for (int i = 0; i < 8; i++)
#pragma unroll
                    for (int j = 0; j < 8; j++)
                        acc[i][j] = fmaf(a[i], b[j], acc[i][j]);
            }
            __syncthreads();
        }

        // epilogue: bias + relu -> g_hn
#pragma unroll
        for (int i = 0; i < 8; i++) {
            int r = ty + 16 * i;
#pragma unroll
            for (int j = 0; j < 8; j++) {
                int d = tx + 16 * j;
                float v = acc[i][j] + bias_s[d];
                g_hn[(size_t)(rowBase + r) * 128 + d] = v > 0.f ? v : 0.f;
            }
        }
        // fall through to streaming tail
    }

    // ---------------- bond_n streaming (ALL blocks) ----------------
    float4 acc[16];
#pragma unroll
    for (int i = 0; i < 16; i++) acc[i] = make_float4(0.f, 0.f, 0.f, 0.f);

    for (int r = 0; r < cnt; r++) {
        const float4* rp = (const float4*)(bn + (size_t)(start + r) * NN) + tid;
#pragma unroll
        for (int i = 0; i < 16; i++) {
            float4 v = __ldcs(rp + i * 256);
            acc[i].x += v.x; acc[i].y += v.y; acc[i].z += v.z; acc[i].w += v.w;
        }
    }
    float4* dst = (float4*)g_part[bid] + tid;
#pragma unroll
    for (int i = 0; i < 16; i++) dst[i * 256] = acc[i];
}

// ---------------------------------------------------------------------------
// k_m (MLP-optimized): 256 blocks, each owns 64 rows of colw.
// Stage 1: colw[n] = sum_u g_part[u][n]; threads split 16 u-segments x
//          16 float4 col-groups -> 18-19 independent float4 loads/thread.
// Stage 2: m partial over the 64 rows -> g_mpartT[d][b] (transposed).
// Last block: contiguous reduce of 256 partials + mm GEMV. Counter resets.
// ---------------------------------------------------------------------------
__global__ void __launch_bounds__(256) k_m(const float* __restrict__ Wm_w2,
                                           const float* __restrict__ Wm_b2) {
    __shared__ float4 sred[16][16];
    __shared__ float colw_s[64];
    __shared__ float red[256];
    __shared__ float ms[128];
    __shared__ bool last;

    const int b = blockIdx.x, tid = threadIdx.x;

    // ---- Stage 1: colw for rows [b*64, b*64+64) ----
    {
        const int seg = tid >> 4;          // 0..15 (u segment)
        const int c4  = tid & 15;          // 0..15 (float4 column group)
        const int u0  = (seg < 8) ? 19 * seg : 152 + 18 * (seg - 8);
        const int un  = (seg < 8) ? 19 : 18;
        float4 s = make_float4(0.f, 0.f, 0.f, 0.f);
#pragma unroll 19
        for (int i = 0; i < un; i++) {
            float4 v = __ldcs((const float4*)(&g_part[u0 + i][b * 64]) + c4);
            s.x += v.x; s.y += v.y; s.z += v.z; s.w += v.w;
        }
        sred[seg][c4] = s;
    }
    __syncthreads();
    if (tid < 16) {
        float4 s = make_float4(0.f, 0.f, 0.f, 0.f);
#pragma unroll
        for (int seg = 0; seg < 16; seg++) {
            float4 v = sred[seg][tid];
            s.x += v.x; s.y += v.y; s.z += v.z; s.w += v.w;
        }
        *(float4*)(colw_s + tid * 4) = s;
    }
    __syncthreads();

    // ---- Stage 2: m partial over this block's 64 rows ----
    const int d = tid & 127, half = tid >> 7;
    float p = 0.f;
#pragma unroll 8
    for (int r = 0; r < 32; r++) {
        int row = half * 32 + r;
        p = fmaf(colw_s[row], g_hn[(size_t)(b * 64 + row) * DD + d], p);
    }
    red[tid] = p;
    __syncthreads();
    if (tid < 128) g_mpartT[tid][b] = red[tid] + red[tid + 128];
    __threadfence();
    if (tid == 0) last = (atomicAdd(&g_cnt, 1u) == MBLK - 1u);
    __syncthreads();

    if (last) {
        if (tid < 128) {
            const float4* mp = (const float4*)g_mpartT[tid];
            float s = 0.f;
#pragma unroll 16
            for (int w = 0; w < MBLK / 4; w++) {
                float4 v = __ldcg(mp + w);
                s += v.x + v.y + v.z + v.w;
            }
            ms[tid] = s;
        }
        __syncthreads();
        if (tid < 128) {
            float s = Wm_b2[tid];
            const float* row = Wm_w2 + tid * 128;
#pragma unroll 8
            for (int k = 0; k < 128; k++) s = fmaf(ms[k], __ldg(row + k), s);
            g_mm[tid] = s;
        }
        if (tid == 0) g_cnt = 0u;   // reset for next graph replay
    }
}

// ---------------------------------------------------------------------------
// k_out: out = relu(h_n + mm[broadcast])
// ---------------------------------------------------------------------------
__global__ void __launch_bounds__(256) k_out(float* __restrict__ out) {
    __shared__ float mm[128];
    if (threadIdx.x < 128) mm[threadIdx.x] = g_mm[threadIdx.x];
    __syncthreads();
    size_t i = (size_t)blockIdx.x * 256 + threadIdx.x;   // float4 index
    float4 v = *(const float4*)(g_hn + i * 4);
    int d0 = (int)((i * 4) & 127);
    v.x = fmaxf(v.x + mm[d0 + 0], 0.f);
    v.y = fmaxf(v.y + mm[d0 + 1], 0.f);
    v.z = fmaxf(v.z + mm[d0 + 2], 0.f);
    v.w = fmaxf(v.w + mm[d0 + 3], 0.f);
    *((float4*)out + i) = v;
}

// ---------------------------------------------------------------------------
extern "C" void kernel_launch(void* const* d_in, const int* in_sizes, int n_in,
                              void* d_out, int out_size) {
    const int*   x    = (const int*)d_in[0];
    const int*   ea   = (const int*)d_in[1];
    const float* bn   = (const float*)d_in[2];
    const float* aemb = (const float*)d_in[3];
    const float* bemb = (const float*)d_in[4];
    const float* Wi_w = (const float*)d_in[5];
    const float* Wi_b = (const float*)d_in[6];
    const float* Wm_w = (const float*)d_in[7];
    const float* Wm_b = (const float*)d_in[8];

    // Only the last layer (i = 2) affects the output.
    const float* Wi_w2 = Wi_w + 2 * 128 * 256;
    const float* Wi_b2 = Wi_b + 2 * 128;
    const float* Wm_w2 = Wm_w + 2 * 128 * 128;
    const float* Wm_b2 = Wm_b + 2 * 128;

    const int smem = (64 * 129 + 128 * 64) * (int)sizeof(float);  // 65,792 B
    static bool attr_set = false;
    if (!attr_set) {
        cudaFuncSetAttribute(k_fused, cudaFuncAttributeMaxDynamicSharedMemorySize, smem);
        attr_set = true;
    }

    k_fused<<<NBLK, 256, smem>>>(bn, x, ea, aemb, bemb, Wi_w2, Wi_b2);
    k_m<<<MBLK, 256>>>(Wm_w2, Wm_b2);
    k_out<<<2048, 256>>>((float*)d_out);
}